// round 4
// baseline (speedup 1.0000x reference)
#include <cuda_runtime.h>
#include <cuda_bf16.h>
#include <cstdint>

// PrRoIPool2D, smem-staged, occupancy-tuned.
// Fixed shapes: features [2, 256, 50, 50] f32, rois [256, 5], out [256,256,7,7] f32.
//
// Block = (roi, 32-channel group), 256 threads, 6 blocks/SM target.
//  1) 14 threads build exact hat-integral 4-tap tables; 1/area folded into wy.
//  2) Stage union window (<=15x15, pitch 15, slab 227 odd) for 32 channels:
//     thread = fixed (h,w), clamped indices (no divergence), unrolled ch loop.
//  3) Compute: lane = channel (stride-227 -> conflict-free), warp shares (p,q).
//  4) float4 transpose-writeback through smem.

#define PH 7
#define PW 7
#define KW 4
#define WIN 15          // window pitch (true window <= 15x15)
#define CG 32
#define SLAB 227        // WIN*WIN + 2, odd (227 mod 32 = 3) -> conflict-free
#define SCALE 0.0625f

#define C_   256
#define H_   50
#define W_   50
#define HW_  (H_ * W_)
#define CHW_ (C_ * HW_)

__device__ __forceinline__ float hat_cdf(float t) {
    t = fminf(fmaxf(t, -1.0f), 1.0f);
    return (t < 0.0f) ? 0.5f * (t + 1.0f) * (t + 1.0f)
                      : 0.5f + t - 0.5f * t * t;
}

__global__ void __launch_bounds__(256, 6)
prroi_pool_kernel(const float* __restrict__ feat,
                  const float* __restrict__ rois,
                  float* __restrict__ out)
{
    const int r  = blockIdx.x >> 3;     // 8 channel groups per roi
    const int cg = blockIdx.x & 7;

    __shared__ __align__(16) float s_win[CG * SLAB];
    __shared__ __align__(16) float s_out[CG * PH * PW];
    __shared__ __align__(16) float s_wy[PH][KW];   // pre-scaled by 1/area
    __shared__ __align__(16) float s_wx[PW][KW];
    __shared__ int   s_i0[2 * PH];      // y0 [0..6], x0 [7..13]
    __shared__ int   s_offy[PH];        // (y0[p]-hstart)*WIN
    __shared__ int   s_offx[PW];        // (x0[q]-wstart)
    __shared__ int   s_base;

    const int tid = threadIdx.x;

    // ---- setup ----
    if (tid < 2 * PH) {
        const float* roi = rois + r * 5;
        const float x1 = roi[1] * SCALE;
        const float y1 = roi[2] * SCALE;
        const float x2 = roi[3] * SCALE;
        const float y2 = roi[4] * SCALE;
        const float bw = (x2 - x1) * (1.0f / PW);
        const float bh = (y2 - y1) * (1.0f / PH);

        const int axis = tid / PH;
        const int p    = tid - axis * PH;
        const float bs = axis ? bw : bh;
        const int   n  = axis ? W_ : H_;
        const float lo = (axis ? x1 : y1) + (float)p * bs;
        const float hi = lo + bs;

        int i0 = (int)ceilf(lo - 1.0f);
        i0 = min(max(i0, 0), n - KW);

        // fold 1/area into the y-axis weights (computed locally: no dependency)
        const float area = bw * bh;
        const float scl  = (axis == 0) ? ((area > 0.0f) ? (1.0f / area) : 0.0f) : 1.0f;

        #pragma unroll
        for (int k = 0; k < KW; k++) {
            const float w = (hat_cdf(hi - (float)(i0 + k)) - hat_cdf(lo - (float)(i0 + k))) * scl;
            if (axis) s_wx[p][k] = w; else s_wy[p][k] = w;
        }
        s_i0[tid] = i0;

        if (tid == 0)
            s_base = (int)roi[0] * CHW_ + cg * (CG * HW_);
    }
    __syncthreads();

    const int hstart = s_i0[0];
    const int wstart = s_i0[PH];

    if (tid < 2 * PH) {
        if (tid < PH) s_offy[tid]      = (s_i0[tid] - hstart) * WIN;
        else          s_offx[tid - PH] =  s_i0[tid] - wstart;
    }

    // ---- stage window: thread = fixed (h,w), clamped (uniform), unrolled ch ----
    {
        const int h = tid >> 4;         // 0..15
        const int w = tid & 15;         // 0..15
        if (h < WIN && w < WIN) {       // static bound, only 31 threads idle
            const int hh = min(hstart + h, H_ - 1);   // clamp: cells beyond the
            const int wc = min(wstart + w, W_ - 1);   // true window are never read
            const float* g = feat + s_base + hh * W_ + wc;
            float* s = s_win + h * WIN + w;
            #pragma unroll
            for (int chn = 0; chn < CG; chn++)
                s[chn * SLAB] = g[chn * HW_];
        }
    }
    __syncthreads();

    // ---- compute: lane = channel, warp shares (p,q) ----
    const int   ch   = tid & 31;
    const int   psel = tid >> 5;
    const float* win = s_win + ch * SLAB;
    float*       so  = s_out + ch * (PH * PW);

    for (int pq = psel; pq < PH * PW; pq += 8) {
        const int p = pq / PW;
        const int q = pq - p * PW;

        const float4 wx = *reinterpret_cast<const float4*>(s_wx[q]);
        const float4 wy = *reinterpret_cast<const float4*>(s_wy[p]);
        const float wya[KW] = { wy.x, wy.y, wy.z, wy.w };

        const float* b = win + s_offy[p] + s_offx[q];

        float acc = 0.0f;
        #pragma unroll
        for (int j = 0; j < KW; j++) {
            const float* row = b + j * WIN;
            float rs = row[0] * wx.x;
            rs  = fmaf(row[1], wx.y, rs);
            rs  = fmaf(row[2], wx.z, rs);
            rs  = fmaf(row[3], wx.w, rs);
            acc = fmaf(wya[j], rs, acc);   // wy pre-scaled by 1/area
        }
        so[pq] = acc;                      // stride 49 (odd): conflict-free
    }
    __syncthreads();

    // ---- float4 coalesced writeback ----
    {
        float4* o4 = reinterpret_cast<float4*>(out + r * (C_ * PH * PW) + cg * (CG * PH * PW));
        const float4* s4 = reinterpret_cast<const float4*>(s_out);
        #pragma unroll
        for (int i = tid; i < (CG * PH * PW) / 4; i += 256)   // 392 float4s
            o4[i] = s4[i];
    }
}

extern "C" void kernel_launch(void* const* d_in, const int* in_sizes, int n_in,
                              void* d_out, int out_size)
{
    const float* feat = (const float*)d_in[0];
    const float* rois = (const float*)d_in[1];
    float* out = (float*)d_out;

    const int R = in_sizes[1] / 5;       // 256
    prroi_pool_kernel<<<R * (C_ / CG), 256>>>(feat, rois, out);
}

// round 5
// speedup vs baseline: 1.1938x; 1.1938x over previous
#include <cuda_runtime.h>
#include <cuda_bf16.h>
#include <cstdint>

// PrRoIPool2D, smem-staged, compact dynamic-pitch window + occupancy 6/SM.
// Fixed shapes: features [2, 256, 50, 50] f32, rois [256, 5], out [256,256,7,7] f32.
//
// Block = (roi, 32-channel group), 256 threads.
//  1) 14 threads build exact hat-integral 4-tap tables (1/area folded into wy)
//     and per-bin word offsets for the dynamic-pitch window.
//  2) Stage ONLY the true union window (wh x ww <= 15x15) for 32 channels into
//     a compact 227-word/channel slab (227 mod 32 = 3 -> conflict-free).
//  3) Compute: lane = channel, warp shares (p,q); 16 LDS.32 + 4 independent
//     row-dot FMA chains per output.
//  4) float4 transpose-writeback through smem.

#define PH 7
#define PW 7
#define KW 4
#define CG 32
#define SLAB 227        // >= 15*15, odd, mod 32 = 3 -> conflict-free lane stride
#define SCALE 0.0625f

#define C_   256
#define H_   50
#define W_   50
#define HW_  (H_ * W_)
#define CHW_ (C_ * HW_)

__device__ __forceinline__ float hat_cdf(float t) {
    t = fminf(fmaxf(t, -1.0f), 1.0f);
    return (t < 0.0f) ? 0.5f * (t + 1.0f) * (t + 1.0f)
                      : 0.5f + t - 0.5f * t * t;
}

__global__ void __launch_bounds__(256, 6)
prroi_pool_kernel(const float* __restrict__ feat,
                  const float* __restrict__ rois,
                  float* __restrict__ out)
{
    const int r  = blockIdx.x >> 3;     // 8 channel groups per roi
    const int cg = blockIdx.x & 7;

    __shared__ __align__(16) float s_win[CG * SLAB];      // 29.1 KB
    __shared__ __align__(16) float s_out[CG * PH * PW];   // 6.3 KB
    __shared__ __align__(16) float s_wy[PH][KW];          // pre-scaled by 1/area
    __shared__ __align__(16) float s_wx[PW][KW];
    __shared__ int   s_i0[2 * PH];      // y0 [0..6], x0 [7..13]
    __shared__ int   s_offy[PH];        // (y0[p]-hstart)*ww
    __shared__ int   s_offx[PW];        // (x0[q]-wstart)
    __shared__ int   s_base;

    const int tid = threadIdx.x;

    // ---- setup: exact per-bin 4-tap hat integrals ----
    if (tid < 2 * PH) {
        const float* roi = rois + r * 5;
        const float x1 = roi[1] * SCALE;
        const float y1 = roi[2] * SCALE;
        const float x2 = roi[3] * SCALE;
        const float y2 = roi[4] * SCALE;
        const float bw = (x2 - x1) * (1.0f / PW);
        const float bh = (y2 - y1) * (1.0f / PH);

        const int axis = tid / PH;
        const int p    = tid - axis * PH;
        const float bs = axis ? bw : bh;
        const int   n  = axis ? W_ : H_;
        const float lo = (axis ? x1 : y1) + (float)p * bs;
        const float hi = lo + bs;

        int i0 = (int)ceilf(lo - 1.0f);
        i0 = min(max(i0, 0), n - KW);

        const float area = bw * bh;
        const float scl  = (axis == 0) ? ((area > 0.0f) ? (1.0f / area) : 0.0f) : 1.0f;

        #pragma unroll
        for (int k = 0; k < KW; k++) {
            const float w = (hat_cdf(hi - (float)(i0 + k)) - hat_cdf(lo - (float)(i0 + k))) * scl;
            if (axis) s_wx[p][k] = w; else s_wy[p][k] = w;
        }
        s_i0[tid] = i0;

        if (tid == 0)
            s_base = (int)roi[0] * CHW_ + cg * (CG * HW_);
    }
    __syncthreads();

    const int hstart = s_i0[0];
    const int wstart = s_i0[PH];
    const int wh = s_i0[PH - 1]     + KW - hstart;   // <= 15
    const int ww = s_i0[2 * PH - 1] + KW - wstart;   // <= 15

    if (tid < 2 * PH) {
        if (tid < PH) s_offy[tid]      = (s_i0[tid] - hstart) * ww;
        else          s_offx[tid - PH] =  s_i0[tid] - wstart;
    }

    // ---- stage true window only: thread = (h,w), unrolled channel loop ----
    {
        const int h = tid >> 4;         // 0..15
        const int w = tid & 15;         // 0..15
        if (h < wh && w < ww) {
            const float* g = feat + s_base + (hstart + h) * W_ + (wstart + w);
            float* s = s_win + h * ww + w;            // compact dynamic pitch
            #pragma unroll
            for (int chn = 0; chn < CG; chn++)
                s[chn * SLAB] = g[chn * HW_];         // constant strides
        }
    }
    __syncthreads();

    // ---- compute: lane = channel, warp shares (p,q) ----
    const int   ch   = tid & 31;
    const int   psel = tid >> 5;
    const float* win = s_win + ch * SLAB;
    float*       so  = s_out + ch * (PH * PW);

    for (int pq = psel; pq < PH * PW; pq += 8) {
        const int p = pq / PW;
        const int q = pq - p * PW;

        const float4 wx = *reinterpret_cast<const float4*>(s_wx[q]);
        const float4 wy = *reinterpret_cast<const float4*>(s_wy[p]);

        const float* b = win + s_offy[p] + s_offx[q];
        const float* r0 = b;
        const float* r1 = b + ww;
        const float* r2 = b + 2 * ww;
        const float* r3 = b + 3 * ww;

        // 4 independent row-dot chains (ILP), then combine with pre-scaled wy
        float a0 = r0[0] * wx.x;
        float a1 = r1[0] * wx.x;
        float a2 = r2[0] * wx.x;
        float a3 = r3[0] * wx.x;
        a0 = fmaf(r0[1], wx.y, a0);  a1 = fmaf(r1[1], wx.y, a1);
        a2 = fmaf(r2[1], wx.y, a2);  a3 = fmaf(r3[1], wx.y, a3);
        a0 = fmaf(r0[2], wx.z, a0);  a1 = fmaf(r1[2], wx.z, a1);
        a2 = fmaf(r2[2], wx.z, a2);  a3 = fmaf(r3[2], wx.z, a3);
        a0 = fmaf(r0[3], wx.w, a0);  a1 = fmaf(r1[3], wx.w, a1);
        a2 = fmaf(r2[3], wx.w, a2);  a3 = fmaf(r3[3], wx.w, a3);

        const float acc = fmaf(wy.x, a0, fmaf(wy.y, a1, fmaf(wy.z, a2, wy.w * a3)));
        so[pq] = acc;                                  // stride 49 (odd): conflict-free
    }
    __syncthreads();

    // ---- float4 coalesced writeback ----
    {
        float4* o4 = reinterpret_cast<float4*>(out + r * (C_ * PH * PW) + cg * (CG * PH * PW));
        const float4* s4 = reinterpret_cast<const float4*>(s_out);
        #pragma unroll
        for (int i = tid; i < (CG * PH * PW) / 4; i += 256)   // 392 float4s
            o4[i] = s4[i];
    }
}

extern "C" void kernel_launch(void* const* d_in, const int* in_sizes, int n_in,
                              void* d_out, int out_size)
{
    const float* feat = (const float*)d_in[0];
    const float* rois = (const float*)d_in[1];
    float* out = (float*)d_out;

    const int R = in_sizes[1] / 5;       // 256
    prroi_pool_kernel<<<R * (C_ / CG), 256>>>(feat, rois, out);
}

// round 6
// speedup vs baseline: 1.3345x; 1.1179x over previous
#include <cuda_runtime.h>
#include <cuda_bf16.h>
#include <cstdint>

// PrRoIPool2D, separable two-pass (y then x) version.
// Fixed shapes: features [2, 256, 50, 50] f32, rois [256, 5], out [256,256,7,7] f32.
//
// Block = (roi, 32-channel group), 256 threads.
//  A) 14 threads compute exact 4-tap hat integrals; 1/area folded into y taps.
//     Threads >=128 zero the scattered row->bin table wyfull[16][8].
//  B) y-taps scattered into wyfull[h][p] (zero elsewhere); x-tables stored.
//  1) y-pass: thread=(x,ch) reads each feature cell ONCE (predicated rows,
//     5-row chunk skipping), accumulates 7 bin sums, writes ytmp[p][ch][x]
//     (pitch 17 -> conflict-free x-pass).
//  2) x-pass: warp=p, lane=ch: 4 LDS + float4 weight per output.
//  3) float4 transpose-writeback through smem.

#define PH 7
#define PW 7
#define KW 4
#define CG 32
#define SCALE 0.0625f
#define YPITCH 17       // 17*lane mod 32 bijective -> conflict-free x-pass

#define C_   256
#define H_   50
#define W_   50
#define HW_  (H_ * W_)
#define CHW_ (C_ * HW_)

__device__ __forceinline__ float hat_cdf(float t) {
    t = fminf(fmaxf(t, -1.0f), 1.0f);
    return (t < 0.0f) ? 0.5f * (t + 1.0f) * (t + 1.0f)
                      : 0.5f + t - 0.5f * t * t;
}

__global__ void __launch_bounds__(256, 6)
prroi_pool_kernel(const float* __restrict__ feat,
                  const float* __restrict__ rois,
                  float* __restrict__ out)
{
    const int r  = blockIdx.x >> 3;     // 8 channel groups per roi
    const int cg = blockIdx.x & 7;

    __shared__ __align__(16) float s_ytmp[PH * CG * YPITCH];   // 15.2 KB
    __shared__ __align__(16) float s_out[CG * PH * PW];        // 6.3 KB
    __shared__ __align__(16) float s_wyfull[16][8];            // [h][p], 1/area folded
    __shared__ __align__(16) float s_wx[PW][KW];
    __shared__ int s_i0[2 * PH];        // y0 [0..6], x0 [7..13]
    __shared__ int s_offx[PW];          // x0[q]-wstart
    __shared__ int s_base;

    const int tid = threadIdx.x;

    // ---- phase A: per-bin taps (registers) + zero wyfull ----
    float taps[KW];
    int   i0 = 0, axis = 0, pp = 0;
    if (tid < 2 * PH) {
        const float* roi = rois + r * 5;
        const float x1 = roi[1] * SCALE;
        const float y1 = roi[2] * SCALE;
        const float x2 = roi[3] * SCALE;
        const float y2 = roi[4] * SCALE;
        const float bw = (x2 - x1) * (1.0f / PW);
        const float bh = (y2 - y1) * (1.0f / PH);

        axis = tid / PH;
        pp   = tid - axis * PH;
        const float bs = axis ? bw : bh;
        const int   n  = axis ? W_ : H_;
        const float lo = (axis ? x1 : y1) + (float)pp * bs;
        const float hi = lo + bs;

        i0 = (int)ceilf(lo - 1.0f);
        i0 = min(max(i0, 0), n - KW);

        const float area = bw * bh;
        const float scl  = axis ? 1.0f : ((area > 0.0f) ? (1.0f / area) : 0.0f);

        #pragma unroll
        for (int k = 0; k < KW; k++)
            taps[k] = (hat_cdf(hi - (float)(i0 + k)) - hat_cdf(lo - (float)(i0 + k))) * scl;

        s_i0[tid] = i0;
        if (tid == 0)
            s_base = (int)roi[0] * CHW_ + cg * (CG * HW_);
    }
    if (tid >= 128 && tid < 128 + 16 * 8) {
        const int z = tid - 128;
        s_wyfull[z >> 3][z & 7] = 0.0f;
    }
    __syncthreads();

    // ---- phase B: scatter y taps, store x tables ----
    if (tid < 2 * PH) {
        if (axis == 0) {
            const int hb = i0 - s_i0[0];
            #pragma unroll
            for (int k = 0; k < KW; k++)
                s_wyfull[hb + k][pp] = taps[k];
        } else {
            s_offx[pp] = i0 - s_i0[PH];
            #pragma unroll
            for (int k = 0; k < KW; k++)
                s_wx[pp][k] = taps[k];
        }
    }
    __syncthreads();

    const int hstart = s_i0[0];
    const int wstart = s_i0[PH];
    const int wh = s_i0[PH - 1]     + KW - hstart;   // <= 15
    const int ww = s_i0[2 * PH - 1] + KW - wstart;   // <= 15

    // ---- y-pass: thread = (x, ch pair), each cell read once ----
    {
        const int lane = tid & 31;
        const int warp = tid >> 5;
        const int x    = lane & 15;                   // 0..15
        const int ch0  = warp * 2 + (lane >> 4);      // 0..15; +16 for second ch
        if (x < ww) {
            const float* g0 = feat + s_base + ch0 * HW_ + hstart * W_ + wstart + x;
            const float* g1 = g0 + 16 * HW_;
            float acc0[PH], acc1[PH];
            #pragma unroll
            for (int p = 0; p < PH; p++) { acc0[p] = 0.0f; acc1[p] = 0.0f; }

            #pragma unroll
            for (int hb = 0; hb < 15; hb += 5) {
                if (hb < wh) {                        // warp-uniform chunk skip
                    float v0[5], v1[5];
                    #pragma unroll
                    for (int j = 0; j < 5; j++) {     // predicated batched loads (MLP=10)
                        const int h = hb + j;
                        const bool in = (h < wh);
                        v0[j] = in ? g0[h * W_] : 0.0f;
                        v1[j] = in ? g1[h * W_] : 0.0f;
                    }
                    #pragma unroll
                    for (int j = 0; j < 5; j++) {
                        const int h = hb + j;
                        const float4 wa = *reinterpret_cast<const float4*>(&s_wyfull[h][0]);
                        const float4 wb = *reinterpret_cast<const float4*>(&s_wyfull[h][4]);
                        acc0[0] = fmaf(v0[j], wa.x, acc0[0]); acc1[0] = fmaf(v1[j], wa.x, acc1[0]);
                        acc0[1] = fmaf(v0[j], wa.y, acc0[1]); acc1[1] = fmaf(v1[j], wa.y, acc1[1]);
                        acc0[2] = fmaf(v0[j], wa.z, acc0[2]); acc1[2] = fmaf(v1[j], wa.z, acc1[2]);
                        acc0[3] = fmaf(v0[j], wa.w, acc0[3]); acc1[3] = fmaf(v1[j], wa.w, acc1[3]);
                        acc0[4] = fmaf(v0[j], wb.x, acc0[4]); acc1[4] = fmaf(v1[j], wb.x, acc1[4]);
                        acc0[5] = fmaf(v0[j], wb.y, acc0[5]); acc1[5] = fmaf(v1[j], wb.y, acc1[5]);
                        acc0[6] = fmaf(v0[j], wb.z, acc0[6]); acc1[6] = fmaf(v1[j], wb.z, acc1[6]);
                    }
                }
            }
            #pragma unroll
            for (int p = 0; p < PH; p++) {
                s_ytmp[(p * CG + ch0)      * YPITCH + x] = acc0[p];
                s_ytmp[(p * CG + ch0 + 16) * YPITCH + x] = acc1[p];
            }
        }
    }
    __syncthreads();

    // ---- x-pass: warp = p, lane = ch ----
    {
        const int lane = tid & 31;
        const int wp   = tid >> 5;
        if (wp < PH) {
            const float* yt = s_ytmp + (wp * CG + lane) * YPITCH;
            float* so = s_out + lane * (PH * PW) + wp * PW;
            #pragma unroll
            for (int q = 0; q < PW; q++) {
                const int xo = s_offx[q];
                const float4 wx = *reinterpret_cast<const float4*>(s_wx[q]);
                float v = yt[xo] * wx.x;
                v = fmaf(yt[xo + 1], wx.y, v);
                v = fmaf(yt[xo + 2], wx.z, v);
                v = fmaf(yt[xo + 3], wx.w, v);
                so[q] = v;                            // lane stride 49 (odd): conflict-free
            }
        }
    }
    __syncthreads();

    // ---- float4 coalesced writeback ----
    {
        float4* o4 = reinterpret_cast<float4*>(out + r * (C_ * PH * PW) + cg * (CG * PH * PW));
        const float4* s4 = reinterpret_cast<const float4*>(s_out);
        #pragma unroll
        for (int i = tid; i < (CG * PH * PW) / 4; i += 256)   // 392 float4s
            o4[i] = s4[i];
    }
}

extern "C" void kernel_launch(void* const* d_in, const int* in_sizes, int n_in,
                              void* d_out, int out_size)
{
    const float* feat = (const float*)d_in[0];
    const float* rois = (const float*)d_in[1];
    float* out = (float*)d_out;

    const int R = in_sizes[1] / 5;       // 256
    prroi_pool_kernel<<<R * (C_ / CG), 256>>>(feat, rois, out);
}